// round 12
// baseline (speedup 1.0000x reference)
#include <cuda_runtime.h>
#include <cuda_bf16.h>
#include <cuda_fp16.h>
#include <math.h>
#include <float.h>
#include <stdint.h>

// ---------------------------------------------------------------------------
// MultiLabelGCN on GB300 — fp16 m16n8k16 fused layers (2 CTAs/SM).
// R12: ONE barrier per K-chunk. Iteration: agg[c] -> wait -> transform
//      in[c+1] -> issue in[c+2] -> bar -> MMA[c]. MMA of stragglers overlaps
//      next chunk's agg/transform of leaders. Chunk-invariant agg indexing
//      hoisted out of the loop.
// ---------------------------------------------------------------------------

#define NUM_JOINTS 33
#define BATCH      4096
#define NN_ROWS    (BATCH * NUM_JOINTS)   // 135168
#define HDIM       256
#define NN_INV     (1.0f / 135168.0f)

#define NTILES (NN_ROWS / 66)       // 2048 CTAs
#define TROWS  66                   // 2 graphs

// smem layout (bytes)
#define OFF_IN     0                        // float [3][66][36]   28512
#define INBUF      9504
#define OFF_A2     28512                    // u32 [2][1280]       10240
#define OFF_SCALE  38752                    // float [256]          1024
#define OFF_SHIFT  39776                    // float [256]          1024
#define OFF_STAT   40800                    // float [512]          2048
#define OFF_NW     42848                    // float [103] + pad     512
#define SMEM_BYTES 43360

__constant__ int ADJ_OFF[34] = {
    0,3,6,9,12,15,18,21,23,25,27,29,33,37,40,43,48,53,56,59,62,65,
    67,69,73,77,80,83,87,91,94,97,100,103};
__constant__ int ADJ_NB[103] = {
    1,4,0,  0,2,1,  1,3,2,  2,7,3,  0,5,4,  4,6,5,  5,8,6,  3,7,  6,8,
    10,9,  9,10,  12,13,23,11,  11,14,24,12,  11,15,13,  12,16,14,
    13,17,19,21,15,  14,18,20,22,16,  15,19,17,  16,20,18,  15,17,19,
    16,18,20,  15,21,  16,22,  11,24,25,23,  12,23,26,24,  23,27,25,
    24,28,26,  25,29,31,27,  26,30,32,28,  27,31,29,  28,32,30,
    29,27,31,  30,28,32};
__constant__ float DEGF[33] = {
    3,3,3,3,3,3,3,2,2,2,2,4,4,3,3,5,5,3,3,3,3,2,2,4,4,3,3,4,4,3,3,3,3};

// scratch
__device__ float g_bufA[(size_t)NN_ROWS * HDIM];
__device__ float g_bufB[(size_t)NN_ROWS * HDIM];
__device__ float g_stats[3 * 512];
__device__ uint2 g_wpackH[4 * 8 * 32 * 2 * 32];  // [mat][chunk][ntile][s][lane]

// ---------------------------------------------------------------------------
__device__ __forceinline__ uint32_t pack_h2(float a, float b) {
    __half2 h = __float22half2_rn(make_float2(a, b));
    return *(uint32_t*)&h;
}
__device__ __forceinline__ void mma_f16(float* d, const uint32_t* a, const uint32_t* b) {
    asm volatile(
        "mma.sync.aligned.m16n8k16.row.col.f32.f16.f16.f32 "
        "{%0,%1,%2,%3}, {%4,%5,%6,%7}, {%8,%9}, {%0,%1,%2,%3};\n"
        : "+f"(d[0]), "+f"(d[1]), "+f"(d[2]), "+f"(d[3])
        : "r"(a[0]), "r"(a[1]), "r"(a[2]), "r"(a[3]), "r"(b[0]), "r"(b[1]));
}
__device__ __forceinline__ void cp16(void* dst, const void* src) {
    uint32_t d = (uint32_t)__cvta_generic_to_shared(dst);
    asm volatile("cp.async.cg.shared.global [%0], [%1], 16;\n" :: "r"(d), "l"(src));
}
#define CP_COMMIT() asm volatile("cp.async.commit_group;\n")
#define CP_WAIT0()  asm volatile("cp.async.wait_group 0;\n")
#define CP_WAIT1()  asm volatile("cp.async.wait_group 1;\n")

__device__ __forceinline__ float fixv(float f) {
    if (isnan(f)) return 0.0f;
    if (isinf(f)) return (f > 0.0f) ? FLT_MAX : -FLT_MAX;
    return f;
}

// ---------------------------------------------------------------------------
// pack weights -> fp16 B fragments (layout verified in R10/R11)
// ---------------------------------------------------------------------------
__global__ void pack_w(const float* __restrict__ w0, const float* __restrict__ w1,
                       const float* __restrict__ w2, const float* __restrict__ wh)
{
    int idx = blockIdx.x * blockDim.x + threadIdx.x;   // 0..65535
    int lane  = idx & 31;
    int s     = (idx >> 5) & 1;
    int ntile = (idx >> 6) & 31;
    int c     = (idx >> 11) & 7;
    int m     = idx >> 14;
    const float* W = (m == 0) ? w0 : (m == 1) ? w1 : (m == 2) ? w2 : wh;
    int k0 = c * 32 + s * 16;
    int n  = ntile * 8 + (lane >> 2);
    int t  = lane & 3;
    uint2 v;
    v.x = pack_h2(W[(size_t)(k0 + 2*t)     * HDIM + n], W[(size_t)(k0 + 2*t + 1) * HDIM + n]);
    v.y = pack_h2(W[(size_t)(k0 + 2*t + 8) * HDIM + n], W[(size_t)(k0 + 2*t + 9) * HDIM + n]);
    g_wpackH[idx] = v;
}

__global__ void zero_stats_kernel(float* stats) {
    int i = blockIdx.x * blockDim.x + threadIdx.x;
    if (i < 3 * 512) stats[i] = 0.0f;
}

// ---------------------------------------------------------------------------
// fused layer. grid = NTILES (2048), block = 256, 2 CTAs/SM.
// ---------------------------------------------------------------------------
__global__ void __launch_bounds__(256, 2)
fused_layer(const float* __restrict__ in, int wsel, const float* __restrict__ bias,
            float* __restrict__ out, const float* __restrict__ stats_in,
            const float* __restrict__ gam, const float* __restrict__ bet,
            float* __restrict__ stats_out, int mode)
{
    extern __shared__ char smem[];
    float*    sIn   = (float*)(smem + OFF_IN);     // [3][66][36]
    uint32_t* sA2   = (uint32_t*)(smem + OFF_A2);  // [2][1280]
    float*    sScale= (float*)(smem + OFF_SCALE);
    float*    sShift= (float*)(smem + OFF_SHIFT);
    float*    sStat = (float*)(smem + OFF_STAT);
    float*    sNW   = (float*)(smem + OFF_NW);

    const int tid = threadIdx.x, lane = tid & 31, warp = tid >> 5;   // 8 warps
    const int p = blockIdx.x;
    const int rowBase = p * TROWS;
    const float* src = in + (size_t)rowBase * HDIM;
    const uint2* wbase = g_wpackH + (size_t)wsel * (8 * 32 * 2 * 32);

    // ---- init ----
    if (tid < NUM_JOINTS) {
        float dn = rsqrtf(DEGF[tid]);
        for (int e = ADJ_OFF[tid]; e < ADJ_OFF[tid + 1]; e++)
            sNW[e] = dn * rsqrtf(DEGF[ADJ_NB[e]]);
    }
    if (mode == 1) {
        float mu  = stats_in[tid] * NN_INV;
        float ex2 = stats_in[256 + tid] * NN_INV;
        float inv = rsqrtf(ex2 - mu * mu + 1e-5f);
        float sc  = inv * gam[tid];
        sScale[tid] = sc;
        sShift[tid] = bet[tid] - mu * sc;
    } else {
        sScale[tid] = 1.0f;
        sShift[tid] = 0.0f;
    }
    sStat[tid] = 0.0f;
    sStat[256 + tid] = 0.0f;
    // zero both A-fragment buffers (pad rows stay zero forever)
    for (int i = tid; i < 2560; i += 256) sA2[i] = 0;

    // ---- hoisted chunk-invariant agg constants (per thread) ----
    const int pair = lane & 15;
    const int half = lane >> 4;
    int e0_[5], e1_[5], lb_[5];
    uint32_t soff_[5];
    bool act_[5];
    #pragma unroll
    for (int j = 0; j < 5; j++) {
        int r = warp + 16 * j + 8 * half;
        act_[j] = (r < TROWS);
        int rr = act_[j] ? r : 0;
        int n  = (rr >= NUM_JOINTS) ? rr - NUM_JOINTS : rr;
        lb_[j] = (rr >= NUM_JOINTS) ? NUM_JOINTS : 0;
        e0_[j] = ADJ_OFF[n];
        e1_[j] = ADJ_OFF[n + 1];
        int tl   = rr >> 4;
        int s    = pair >> 3;
        int lp   = (rr & 7) * 4 + (pair & 3);
        int comp = ((rr >> 3) & 1) + (((pair >> 2) & 1) << 1);
        soff_[j] = ((tl * 2 + s) * 32 + lp) * 4 + comp;
    }

    // ---- prologue: stage in[0], in[1]; transform in[0] ----
    for (int j = tid; j < TROWS * 8; j += 256) {
        int r = j >> 3, seg = j & 7;
        cp16((char*)sIn + r * 144 + seg * 16, src + (size_t)r * HDIM + seg * 4);
    }
    CP_COMMIT();
    for (int j = tid; j < TROWS * 8; j += 256) {
        int r = j >> 3, seg = j & 7;
        cp16((char*)sIn + INBUF + r * 144 + seg * 16,
             src + (size_t)r * HDIM + 32 + seg * 4);
    }
    CP_COMMIT();
    CP_WAIT1();
    __syncthreads();   // init + in[0] visible

    // transform in[0] (chunk 0 channels)
    for (int j = tid; j < 1056; j += 256) {
        int r = j >> 4, pr = j & 15;
        float2* a = (float2*)&sIn[r * 36 + pr * 2];
        float2 f = *a;
        if (mode == 0) {
            f.x = fixv(f.x); f.y = fixv(f.y);
        } else {
            float2 sc = *(const float2*)&sScale[pr * 2];
            float2 sh = *(const float2*)&sShift[pr * 2];
            f.x = fmaxf(fmaf(f.x, sc.x, sh.x), 0.0f);
            f.y = fmaxf(fmaf(f.y, sc.y, sh.y), 0.0f);
        }
        *a = f;
    }
    __syncthreads();   // transformed in[0] visible

    float acc[5][4][4];
    #pragma unroll
    for (int i = 0; i < 5; i++)
        #pragma unroll
        for (int nt = 0; nt < 4; nt++)
            #pragma unroll
            for (int j = 0; j < 4; j++) acc[i][nt][j] = 0.0f;

    for (int c = 0; c < 8; c++) {
        // ---- B[c] prefetch (L2 latency hides under agg + transform) ----
        uint2 bfr[2][4];
        #pragma unroll
        for (int s = 0; s < 2; s++)
            #pragma unroll
            for (int nt = 0; nt < 4; nt++)
                bfr[s][nt] = __ldg(&wbase[((c * 32 + warp * 4 + nt) * 2 + s) * 32 + lane]);

        // ---- agg[c]: transformed in[c] -> sA2[c&1] fragments ----
        {
            const float* sInc = sIn + (c % 3) * (66 * 36);
            uint32_t* sAc = sA2 + (c & 1) * 1280;
            #pragma unroll
            for (int j = 0; j < 5; j++) {
                if (act_[j]) {
                    float ax = 0.0f, ay = 0.0f;
                    for (int e = e0_[j]; e < e1_[j]; e++) {
                        float2 f = *(const float2*)&sInc[(lb_[j] + ADJ_NB[e]) * 36 + pair * 2];
                        float w = sNW[e];
                        ax = fmaf(w, f.x, ax);
                        ay = fmaf(w, f.y, ay);
                    }
                    sAc[soff_[j]] = pack_h2(ax, ay);
                }
            }
        }

        // ---- wait in[c+1] staged, transform it ----
        CP_WAIT0();
        if (c + 1 < 8) {
            float* sT = sIn + ((c + 1) % 3) * (66 * 36);
            const int cb = (c + 1) * 32;
            for (int j = tid; j < 1056; j += 256) {
                int r = j >> 4, pr = j & 15;
                float2* a = (float2*)&sT[r * 36 + pr * 2];
                float2 f = *a;
                if (mode == 0) {
                    f.x = fixv(f.x); f.y = fixv(f.y);
                } else {
                    float2 sc = *(const float2*)&sScale[cb + pr * 2];
                    float2 sh = *(const float2*)&sShift[cb + pr * 2];
                    f.x = fmaxf(fmaf(f.x, sc.x, sh.x), 0.0f);
                    f.y = fmaxf(fmaf(f.y, sc.y, sh.y), 0.0f);
                }
                *a = f;
            }
        }

        // ---- issue in[c+2] (victim buffer read by agg[c-1], pre-barrier) ----
        if (c + 2 < 8) {
            char* dI = (char*)sIn + ((c + 2) % 3) * INBUF;
            const float* sN = src + (c + 2) * 32;
            for (int j = tid; j < TROWS * 8; j += 256) {
                int r = j >> 3, seg = j & 7;
                cp16(dI + r * 144 + seg * 16, sN + (size_t)r * HDIM + seg * 4);
            }
        }
        CP_COMMIT();       // unconditional: uniform group accounting

        __syncthreads();   // THE barrier: sA2[c&1] + transformed in[c+1] visible

        // ---- MMA[c]: A LDS.128 from smem, B from prefetched registers ----
        {
            const uint32_t* sAc = sA2 + (c & 1) * 1280;
            #pragma unroll
            for (int s = 0; s < 2; s++) {
                #pragma unroll
                for (int tl = 0; tl < 5; tl++) {
                    uint4 av = *(const uint4*)&sAc[((tl * 2 + s) * 32 + lane) * 4];
                    const uint32_t* af = (const uint32_t*)&av;
                    #pragma unroll
                    for (int nt = 0; nt < 4; nt++)
                        mma_f16(acc[tl][nt], af, (const uint32_t*)&bfr[s][nt]);
                }
            }
        }
    }

    // ---- epilogue: bias, store, stats (warp covers cols warp*32..+31) ----
    float bval[8];
    #pragma unroll
    for (int nt = 0; nt < 4; nt++) {
        int col = warp * 32 + nt * 8 + 2 * (lane & 3);
        bval[nt * 2 + 0] = bias[col];
        bval[nt * 2 + 1] = bias[col + 1];
    }
    float cs1[8], cs2[8];
    #pragma unroll
    for (int j = 0; j < 8; j++) { cs1[j] = 0.0f; cs2[j] = 0.0f; }

    #pragma unroll
    for (int i = 0; i < 5; i++) {
        int rb = i * 16 + (lane >> 2);
        #pragma unroll
        for (int nt = 0; nt < 4; nt++) {
            int col = warp * 32 + nt * 8 + 2 * (lane & 3);
            if (rb < TROWS) {
                float z0 = acc[i][nt][0] + bval[nt * 2 + 0];
                float z1 = acc[i][nt][1] + bval[nt * 2 + 1];
                *(float2*)(out + (size_t)(rowBase + rb) * HDIM + col) = make_float2(z0, z1);
                cs1[nt * 2 + 0] += z0; cs2[nt * 2 + 0] = fmaf(z0, z0, cs2[nt * 2 + 0]);
                cs1[nt * 2 + 1] += z1; cs2[nt * 2 + 1] = fmaf(z1, z1, cs2[nt * 2 + 1]);
            }
            int r2 = rb + 8;
            if (r2 < TROWS) {
                float z2 = acc[i][nt][2] + bval[nt * 2 + 0];
                float z3 = acc[i][nt][3] + bval[nt * 2 + 1];
                *(float2*)(out + (size_t)(rowBase + r2) * HDIM + col) = make_float2(z2, z3);
                cs1[nt * 2 + 0] += z2; cs2[nt * 2 + 0] = fmaf(z2, z2, cs2[nt * 2 + 0]);
                cs1[nt * 2 + 1] += z3; cs2[nt * 2 + 1] = fmaf(z3, z3, cs2[nt * 2 + 1]);
            }
        }
    }

    if (stats_out != nullptr) {
        #pragma unroll
        for (int j = 0; j < 8; j++) {
            int cl = warp * 32 + (j >> 1) * 8 + 2 * (lane & 3) + (j & 1);
            atomicAdd(&sStat[cl], cs1[j]);
            atomicAdd(&sStat[256 + cl], cs2[j]);
        }
        __syncthreads();
        atomicAdd(&stats_out[tid], sStat[tid]);
        atomicAdd(&stats_out[256 + tid], sStat[256 + tid]);
    }
}

// ---------------------------------------------------------------------------
__global__ void __launch_bounds__(256)
pool_kernel(const float* __restrict__ h, const float* __restrict__ wc,
            const float* __restrict__ bc, float* __restrict__ out)
{
    const int g = blockIdx.x;
    const int tid = threadIdx.x;
    const int lane = tid & 31, warp = tid >> 5;
    const size_t base = (size_t)g * NUM_JOINTS * HDIM;

    float s = 0.0f;
    #pragma unroll
    for (int n = 0; n < NUM_JOINTS; n++) s += h[base + n * HDIM + tid];
    s *= (1.0f / 33.0f);

    float4 wv = *(const float4*)(wc + tid * 4);
    float p0 = s * wv.x, p1 = s * wv.y, p2 = s * wv.z, p3 = s * wv.w;
    #pragma unroll
    for (int off = 16; off > 0; off >>= 1) {
        p0 += __shfl_down_sync(0xFFFFFFFF, p0, off);
        p1 += __shfl_down_sync(0xFFFFFFFF, p1, off);
        p2 += __shfl_down_sync(0xFFFFFFFF, p2, off);
        p3 += __shfl_down_sync(0xFFFFFFFF, p3, off);
    }
    __shared__ float4 part[8];
    if (lane == 0) part[warp] = make_float4(p0, p1, p2, p3);
    __syncthreads();
    if (tid == 0) {
        float4 o = make_float4(bc[0], bc[1], bc[2], bc[3]);
        #pragma unroll
        for (int w = 0; w < 8; w++) {
            o.x += part[w].x; o.y += part[w].y; o.z += part[w].z; o.w += part[w].w;
        }
        *(float4*)(out + g * 4) = o;
    }
}

// ---------------------------------------------------------------------------
extern "C" void kernel_launch(void* const* d_in, const int* in_sizes, int n_in,
                              void* d_out, int out_size)
{
    const float* x   = (const float*)d_in[0];
    const float* w0  = (const float*)d_in[1];
    const float* b0  = (const float*)d_in[2];
    const float* g0  = (const float*)d_in[3];
    const float* be0 = (const float*)d_in[4];
    const float* w1  = (const float*)d_in[5];
    const float* b1  = (const float*)d_in[6];
    const float* g1  = (const float*)d_in[7];
    const float* be1 = (const float*)d_in[8];
    const float* w2  = (const float*)d_in[9];
    const float* b2  = (const float*)d_in[10];
    const float* g2  = (const float*)d_in[11];
    const float* be2 = (const float*)d_in[12];
    const float* wh  = (const float*)d_in[13];
    const float* bh  = (const float*)d_in[14];
    const float* wc  = (const float*)d_in[15];
    const float* bc  = (const float*)d_in[16];

    float *bufA, *bufB, *stats;
    cudaGetSymbolAddress((void**)&bufA, g_bufA);
    cudaGetSymbolAddress((void**)&bufB, g_bufB);
    cudaGetSymbolAddress((void**)&stats, g_stats);

    cudaFuncSetAttribute(fused_layer, cudaFuncAttributeMaxDynamicSharedMemorySize,
                         SMEM_BYTES);

    pack_w<<<256, 256>>>(w0, w1, w2, wh);
    zero_stats_kernel<<<6, 256>>>(stats);

    fused_layer<<<NTILES, 256, SMEM_BYTES>>>(x,    0, b0, bufB, nullptr, nullptr, nullptr, stats, 0);
    fused_layer<<<NTILES, 256, SMEM_BYTES>>>(bufB, 1, b1, bufA, stats,        g0, be0, stats + 512, 1);
    fused_layer<<<NTILES, 256, SMEM_BYTES>>>(bufA, 2, b2, bufB, stats + 512,  g1, be1, stats + 1024, 1);
    fused_layer<<<NTILES, 256, SMEM_BYTES>>>(bufB, 3, bh, bufA, stats + 1024, g2, be2, nullptr, 1);
    pool_kernel<<<BATCH, 256>>>(bufA, wc, bc, (float*)d_out);
}

// round 13
// speedup vs baseline: 1.0325x; 1.0325x over previous
#include <cuda_runtime.h>
#include <cuda_bf16.h>
#include <cuda_fp16.h>
#include <math.h>
#include <float.h>
#include <stdint.h>

// ---------------------------------------------------------------------------
// MultiLabelGCN on GB300 — fp16 m16n8k16 fused layers (2 CTAs/SM).
// R13: R11 pipeline with BK=64 (4 chunks instead of 8) -> half the barriers.
//      B fragments prefetched in two halves (s01 before agg, s23 after bar3).
// ---------------------------------------------------------------------------

#define NUM_JOINTS 33
#define BATCH      4096
#define NN_ROWS    (BATCH * NUM_JOINTS)   // 135168
#define HDIM       256
#define NN_INV     (1.0f / 135168.0f)

#define NTILES (NN_ROWS / 66)       // 2048 CTAs
#define TROWS  66                   // 2 graphs
#define NCHUNK 4                    // K chunks of 64

// smem layout (bytes)
#define OFF_IN     0                        // float [3][66][72]   57024
#define INBUF      19008
#define OFF_A2     57024                    // u32 [2][2560]       20480
#define OFF_SCALE  77504                    // float [256]          1024
#define OFF_SHIFT  78528                    // float [256]          1024
#define OFF_STAT   79552                    // float [512]          2048
#define OFF_NW     81600                    // float [103] + pad     512
#define SMEM_BYTES 82112

__constant__ int ADJ_OFF[34] = {
    0,3,6,9,12,15,18,21,23,25,27,29,33,37,40,43,48,53,56,59,62,65,
    67,69,73,77,80,83,87,91,94,97,100,103};
__constant__ int ADJ_NB[103] = {
    1,4,0,  0,2,1,  1,3,2,  2,7,3,  0,5,4,  4,6,5,  5,8,6,  3,7,  6,8,
    10,9,  9,10,  12,13,23,11,  11,14,24,12,  11,15,13,  12,16,14,
    13,17,19,21,15,  14,18,20,22,16,  15,19,17,  16,20,18,  15,17,19,
    16,18,20,  15,21,  16,22,  11,24,25,23,  12,23,26,24,  23,27,25,
    24,28,26,  25,29,31,27,  26,30,32,28,  27,31,29,  28,32,30,
    29,27,31,  30,28,32};
__constant__ float DEGF[33] = {
    3,3,3,3,3,3,3,2,2,2,2,4,4,3,3,5,5,3,3,3,3,2,2,4,4,3,3,4,4,3,3,3,3};

// scratch
__device__ float g_bufA[(size_t)NN_ROWS * HDIM];
__device__ float g_bufB[(size_t)NN_ROWS * HDIM];
__device__ float g_stats[3 * 512];
__device__ uint2 g_wpackH[4 * 8 * 32 * 2 * 32];  // [mat][chunk32][ntile][s][lane]

// ---------------------------------------------------------------------------
__device__ __forceinline__ uint32_t pack_h2(float a, float b) {
    __half2 h = __float22half2_rn(make_float2(a, b));
    return *(uint32_t*)&h;
}
__device__ __forceinline__ void mma_f16(float* d, const uint32_t* a, const uint32_t* b) {
    asm volatile(
        "mma.sync.aligned.m16n8k16.row.col.f32.f16.f16.f32 "
        "{%0,%1,%2,%3}, {%4,%5,%6,%7}, {%8,%9}, {%0,%1,%2,%3};\n"
        : "+f"(d[0]), "+f"(d[1]), "+f"(d[2]), "+f"(d[3])
        : "r"(a[0]), "r"(a[1]), "r"(a[2]), "r"(a[3]), "r"(b[0]), "r"(b[1]));
}
__device__ __forceinline__ void cp16(void* dst, const void* src) {
    uint32_t d = (uint32_t)__cvta_generic_to_shared(dst);
    asm volatile("cp.async.cg.shared.global [%0], [%1], 16;\n" :: "r"(d), "l"(src));
}
#define CP_COMMIT() asm volatile("cp.async.commit_group;\n")
#define CP_WAIT1()  asm volatile("cp.async.wait_group 1;\n")

__device__ __forceinline__ float fixv(float f) {
    if (isnan(f)) return 0.0f;
    if (isinf(f)) return (f > 0.0f) ? FLT_MAX : -FLT_MAX;
    return f;
}

// ---------------------------------------------------------------------------
// pack weights -> fp16 B fragments (32-chunk layout, verified R10-R12)
// ---------------------------------------------------------------------------
__global__ void pack_w(const float* __restrict__ w0, const float* __restrict__ w1,
                       const float* __restrict__ w2, const float* __restrict__ wh)
{
    int idx = blockIdx.x * blockDim.x + threadIdx.x;   // 0..65535
    int lane  = idx & 31;
    int s     = (idx >> 5) & 1;
    int ntile = (idx >> 6) & 31;
    int c     = (idx >> 11) & 7;
    int m     = idx >> 14;
    const float* W = (m == 0) ? w0 : (m == 1) ? w1 : (m == 2) ? w2 : wh;
    int k0 = c * 32 + s * 16;
    int n  = ntile * 8 + (lane >> 2);
    int t  = lane & 3;
    uint2 v;
    v.x = pack_h2(W[(size_t)(k0 + 2*t)     * HDIM + n], W[(size_t)(k0 + 2*t + 1) * HDIM + n]);
    v.y = pack_h2(W[(size_t)(k0 + 2*t + 8) * HDIM + n], W[(size_t)(k0 + 2*t + 9) * HDIM + n]);
    g_wpackH[idx] = v;
}

__global__ void zero_stats_kernel(float* stats) {
    int i = blockIdx.x * blockDim.x + threadIdx.x;
    if (i < 3 * 512) stats[i] = 0.0f;
}

// ---------------------------------------------------------------------------
// fused layer. grid = NTILES (2048), block = 256, 2 CTAs/SM.
// ---------------------------------------------------------------------------
__global__ void __launch_bounds__(256, 2)
fused_layer(const float* __restrict__ in, int wsel, const float* __restrict__ bias,
            float* __restrict__ out, const float* __restrict__ stats_in,
            const float* __restrict__ gam, const float* __restrict__ bet,
            float* __restrict__ stats_out, int mode)
{
    extern __shared__ char smem[];
    float*    sIn   = (float*)(smem + OFF_IN);     // [3][66][72]
    uint32_t* sA2   = (uint32_t*)(smem + OFF_A2);  // [2][2560]
    float*    sScale= (float*)(smem + OFF_SCALE);
    float*    sShift= (float*)(smem + OFF_SHIFT);
    float*    sStat = (float*)(smem + OFF_STAT);
    float*    sNW   = (float*)(smem + OFF_NW);

    const int tid = threadIdx.x, lane = tid & 31, warp = tid >> 5;   // 8 warps
    const int p = blockIdx.x;
    const int rowBase = p * TROWS;
    const float* src = in + (size_t)rowBase * HDIM;
    const uint2* wbase = g_wpackH + (size_t)wsel * (8 * 32 * 2 * 32);

    // ---- init ----
    if (tid < NUM_JOINTS) {
        float dn = rsqrtf(DEGF[tid]);
        for (int e = ADJ_OFF[tid]; e < ADJ_OFF[tid + 1]; e++)
            sNW[e] = dn * rsqrtf(DEGF[ADJ_NB[e]]);
    }
    if (mode == 1) {
        float mu  = stats_in[tid] * NN_INV;
        float ex2 = stats_in[256 + tid] * NN_INV;
        float inv = rsqrtf(ex2 - mu * mu + 1e-5f);
        float sc  = inv * gam[tid];
        sScale[tid] = sc;
        sShift[tid] = bet[tid] - mu * sc;
    } else {
        sScale[tid] = 1.0f;
        sShift[tid] = 0.0f;
    }
    sStat[tid] = 0.0f;
    sStat[256 + tid] = 0.0f;
    // zero both A-fragment buffers (pad rows stay zero forever)
    for (int i = tid; i < 5120; i += 256) sA2[i] = 0;

    // ---- hoisted chunk-invariant agg constants ----
    const int pair = lane & 15;
    const int half = lane >> 4;
    int e0_[5], e1_[5], lb_[5];
    uint32_t soff_[5][2];
    bool act_[5];
    #pragma unroll
    for (int j = 0; j < 5; j++) {
        int r = warp + 16 * j + 8 * half;
        act_[j] = (r < TROWS);
        int rr = act_[j] ? r : 0;
        int n  = (rr >= NUM_JOINTS) ? rr - NUM_JOINTS : rr;
        lb_[j] = (rr >= NUM_JOINTS) ? NUM_JOINTS : 0;
        e0_[j] = ADJ_OFF[n];
        e1_[j] = ADJ_OFF[n + 1];
        #pragma unroll
        for (int h2 = 0; h2 < 2; h2++) {
            int pi   = pair + 16 * h2;
            int tl   = rr >> 4;
            int sg   = pi >> 3;
            int lp   = (rr & 7) * 4 + (pi & 3);
            int comp = ((rr >> 3) & 1) + (((pi >> 2) & 1) << 1);
            soff_[j][h2] = ((tl * 4 + sg) * 32 + lp) * 4 + comp;
        }
    }

    // ---- prologue: stage in[0], in[1] (66 rows x 64 chans each) ----
    for (int j = tid; j < TROWS * 16; j += 256) {
        int r = j >> 4, seg = j & 15;
        cp16((char*)sIn + r * 288 + seg * 16, src + (size_t)r * HDIM + seg * 4);
    }
    CP_COMMIT();
    for (int j = tid; j < TROWS * 16; j += 256) {
        int r = j >> 4, seg = j & 15;
        cp16((char*)sIn + INBUF + r * 288 + seg * 16,
             src + (size_t)r * HDIM + 64 + seg * 4);
    }
    CP_COMMIT();

    float acc[5][4][4];
    #pragma unroll
    for (int i = 0; i < 5; i++)
        #pragma unroll
        for (int nt = 0; nt < 4; nt++)
            #pragma unroll
            for (int j = 0; j < 4; j++) acc[i][nt][j] = 0.0f;

    for (int c = 0; c < NCHUNK; c++) {
        CP_WAIT1();
        __syncthreads();   // bar1: in[c] staged+visible; MMA[c-1] retired

        // ---- B[c] s=0,1 prefetch (hides under transform + agg) ----
        uint2 bfr01[2][4];
        #pragma unroll
        for (int s = 0; s < 2; s++)
            #pragma unroll
            for (int nt = 0; nt < 4; nt++)
                bfr01[s][nt] = __ldg(&wbase[(((c * 2) * 32 + warp * 4 + nt) * 2 + s) * 32 + lane]);

        // ---- transform in[c] IN PLACE ----
        {
            float* sInc = sIn + (c % 3) * (66 * 72);
            const int cb = c * 64;
            for (int j = tid; j < 2112; j += 256) {      // 66 rows x 32 pairs
                int r = j >> 5, pr = j & 31;
                float2* a = (float2*)&sInc[r * 72 + pr * 2];
                float2 f = *a;
                if (mode == 0) {
                    f.x = fixv(f.x); f.y = fixv(f.y);
                } else {
                    float2 sc = *(const float2*)&sScale[cb + pr * 2];
                    float2 sh = *(const float2*)&sShift[cb + pr * 2];
                    f.x = fmaxf(fmaf(f.x, sc.x, sh.x), 0.0f);
                    f.y = fmaxf(fmaf(f.y, sc.y, sh.y), 0.0f);
                }
                *a = f;
            }
        }

        // issue in[c+2]
        if (c + 2 < NCHUNK) {
            char* dI = (char*)sIn + ((c + 2) % 3) * INBUF;
            const float* sN = src + (c + 2) * 64;
            for (int j = tid; j < TROWS * 16; j += 256) {
                int r = j >> 4, seg = j & 15;
                cp16(dI + r * 288 + seg * 16, sN + (size_t)r * HDIM + seg * 4);
            }
        }
        CP_COMMIT();       // unconditional: uniform group accounting

        __syncthreads();   // bar2: transformed in[c] visible

        // ---- agg[c]: pure stencil, 2 channel-halves per thread ----
        {
            const float* sInc = sIn + (c % 3) * (66 * 72);
            uint32_t* sAc = sA2 + (c & 1) * 2560;
            #pragma unroll
            for (int j = 0; j < 5; j++) {
                if (act_[j]) {
                    float ax0 = 0.0f, ay0 = 0.0f, ax1 = 0.0f, ay1 = 0.0f;
                    for (int e = e0_[j]; e < e1_[j]; e++) {
                        const float* b = &sInc[(lb_[j] + ADJ_NB[e]) * 72];
                        float2 f0 = *(const float2*)&b[pair * 2];
                        float2 f1 = *(const float2*)&b[(pair + 16) * 2];
                        float w = sNW[e];
                        ax0 = fmaf(w, f0.x, ax0);
                        ay0 = fmaf(w, f0.y, ay0);
                        ax1 = fmaf(w, f1.x, ax1);
                        ay1 = fmaf(w, f1.y, ay1);
                    }
                    sAc[soff_[j][0]] = pack_h2(ax0, ay0);
                    sAc[soff_[j][1]] = pack_h2(ax1, ay1);
                }
            }
        }
        __syncthreads();   // bar3: sA2[c&1] ready

        // ---- MMA[c]: issue s=2,3 B loads, then 4 k16 steps ----
        {
            const uint32_t* sAc = sA2 + (c & 1) * 2560;
            uint2 bfr23[2][4];
            #pragma unroll
            for (int s = 0; s < 2; s++)
                #pragma unroll
                for (int nt = 0; nt < 4; nt++)
                    bfr23[s][nt] = __ldg(&wbase[(((c * 2 + 1) * 32 + warp * 4 + nt) * 2 + s) * 32 + lane]);

            #pragma unroll
            for (int sg = 0; sg < 4; sg++) {
                const uint2* bf = (sg < 2) ? bfr01[sg] : bfr23[sg - 2];
                #pragma unroll
                for (int tl = 0; tl < 5; tl++) {
                    uint4 av = *(const uint4*)&sAc[((tl * 4 + sg) * 32 + lane) * 4];
                    const uint32_t* af = (const uint32_t*)&av;
                    #pragma unroll
                    for (int nt = 0; nt < 4; nt++)
                        mma_f16(acc[tl][nt], af, (const uint32_t*)&bf[nt]);
                }
            }
        }
    }

    // ---- epilogue: bias, store, stats (warp covers cols warp*32..+31) ----
    float bval[8];
    #pragma unroll
    for (int nt = 0; nt < 4; nt++) {
        int col = warp * 32 + nt * 8 + 2 * (lane & 3);
        bval[nt * 2 + 0] = bias[col];
        bval[nt * 2 + 1] = bias[col + 1];
    }
    float cs1[8], cs2[8];
    #pragma unroll
    for (int j = 0; j < 8; j++) { cs1[j] = 0.0f; cs2[j] = 0.0f; }

    #pragma unroll
    for (int i = 0; i < 5; i++) {
        int rb = i * 16 + (lane >> 2);
        #pragma unroll
        for (int nt = 0; nt < 4; nt++) {
            int col = warp * 32 + nt * 8 + 2 * (lane & 3);
            if (rb < TROWS) {
                float z0 = acc[i][nt][0] + bval[nt * 2 + 0];
                float z1 = acc[i][nt][1] + bval[nt * 2 + 1];
                *(float2*)(out + (size_t)(rowBase + rb) * HDIM + col) = make_float2(z0, z1);
                cs1[nt * 2 + 0] += z0; cs2[nt * 2 + 0] = fmaf(z0, z0, cs2[nt * 2 + 0]);
                cs1[nt * 2 + 1] += z1; cs2[nt * 2 + 1] = fmaf(z1, z1, cs2[nt * 2 + 1]);
            }
            int r2 = rb + 8;
            if (r2 < TROWS) {
                float z2 = acc[i][nt][2] + bval[nt * 2 + 0];
                float z3 = acc[i][nt][3] + bval[nt * 2 + 1];
                *(float2*)(out + (size_t)(rowBase + r2) * HDIM + col) = make_float2(z2, z3);
                cs1[nt * 2 + 0] += z2; cs2[nt * 2 + 0] = fmaf(z2, z2, cs2[nt * 2 + 0]);
                cs1[nt * 2 + 1] += z3; cs2[nt * 2 + 1] = fmaf(z3, z3, cs2[nt * 2 + 1]);
            }
        }
    }

    if (stats_out != nullptr) {
        #pragma unroll
        for (int j = 0; j < 8; j++) {
            int cl = warp * 32 + (j >> 1) * 8 + 2 * (lane & 3) + (j & 1);
            atomicAdd(&sStat[cl], cs1[j]);
            atomicAdd(&sStat[256 + cl], cs2[j]);
        }
        __syncthreads();
        atomicAdd(&stats_out[tid], sStat[tid]);
        atomicAdd(&stats_out[256 + tid], sStat[256 + tid]);
    }
}

// ---------------------------------------------------------------------------
__global__ void __launch_bounds__(256)
pool_kernel(const float* __restrict__ h, const float* __restrict__ wc,
            const float* __restrict__ bc, float* __restrict__ out)
{
    const int g = blockIdx.x;
    const int tid = threadIdx.x;
    const int lane = tid & 31, warp = tid >> 5;
    const size_t base = (size_t)g * NUM_JOINTS * HDIM;

    float s = 0.0f;
    #pragma unroll
    for (int n = 0; n < NUM_JOINTS; n++) s += h[base + n * HDIM + tid];
    s *= (1.0f / 33.0f);

    float4 wv = *(const float4*)(wc + tid * 4);
    float p0 = s * wv.x, p1 = s * wv.y, p2 = s * wv.z, p3 = s * wv.w;
    #pragma unroll
    for (int off = 16; off > 0; off >>= 1) {
        p0 += __shfl_down_sync(0xFFFFFFFF, p0, off);
        p1 += __shfl_down_sync(0xFFFFFFFF, p1, off);
        p2 += __shfl_down_sync(0xFFFFFFFF, p2, off);
        p3 += __shfl_down_sync(0xFFFFFFFF, p3, off);
    }
    __shared__ float4 part[8];
    if (lane == 0) part[warp] = make_float4(p0, p1, p2, p3);
    __syncthreads();
    if (tid == 0) {
        float4 o = make_float4(bc[0], bc[1], bc[2], bc[3]);
        #pragma unroll
        for (int w = 0; w < 8; w++) {
            o.x += part[w].x; o.y += part[w].y; o.z += part[w].z; o.w += part[w].w;
        }
        *(float4*)(out + g * 4) = o;
    }
}

// ---------------------------------------------------------------------------
extern "C" void kernel_launch(void* const* d_in, const int* in_sizes, int n_in,
                              void* d_out, int out_size)
{
    const float* x   = (const float*)d_in[0];
    const float* w0  = (const float*)d_in[1];
    const float* b0  = (const float*)d_in[2];
    const float* g0  = (const float*)d_in[3];
    const float* be0 = (const float*)d_in[4];
    const float* w1  = (const float*)d_in[5];
    const float* b1  = (const float*)d_in[6];
    const float* g1  = (const float*)d_in[7];
    const float* be1 = (const float*)d_in[8];
    const float* w2  = (const float*)d_in[9];
    const float* b2  = (const float*)d_in[10];
    const float* g2  = (const float*)d_in[11];
    const float* be2 = (const float*)d_in[12];
    const float* wh  = (const float*)d_in[13];
    const float* bh  = (const float*)d_in[14];
    const float* wc  = (const float*)d_in[15];
    const float* bc  = (const float*)d_in[16];

    float *bufA, *bufB, *stats;
    cudaGetSymbolAddress((void**)&bufA, g_bufA);
    cudaGetSymbolAddress((void**)&bufB, g_bufB);
    cudaGetSymbolAddress((void**)&stats, g_stats);

    cudaFuncSetAttribute(fused_layer, cudaFuncAttributeMaxDynamicSharedMemorySize,
                         SMEM_BYTES);

    pack_w<<<256, 256>>>(w0, w1, w2, wh);
    zero_stats_kernel<<<6, 256>>>(stats);

    fused_layer<<<NTILES, 256, SMEM_BYTES>>>(x,    0, b0, bufB, nullptr, nullptr, nullptr, stats, 0);
    fused_layer<<<NTILES, 256, SMEM_BYTES>>>(bufB, 1, b1, bufA, stats,        g0, be0, stats + 512, 1);
    fused_layer<<<NTILES, 256, SMEM_BYTES>>>(bufA, 2, b2, bufB, stats + 512,  g1, be1, stats + 1024, 1);
    fused_layer<<<NTILES, 256, SMEM_BYTES>>>(bufB, 3, bh, bufA, stats + 1024, g2, be2, nullptr, 1);
    pool_kernel<<<BATCH, 256>>>(bufA, wc, bc, (float*)d_out);
}